// round 3
// baseline (speedup 1.0000x reference)
#include <cuda_runtime.h>

#define BB   512
#define CC   512
#define KK   512
#define EE   16
#define NT   128

#define Z_OFF   0
#define ZE_OFF  ((size_t)BB * CC * EE)            // 4,194,304 floats
#define OH_OFF  ((size_t)2 * BB * CC * EE)        // 8,388,608 floats

typedef unsigned long long u64;

__device__ __forceinline__ u64 pack2(float a, float b) {
    u64 r;
    asm("mov.b64 %0, {%1, %2};" : "=l"(r) : "f"(a), "f"(b));
    return r;
}
__device__ __forceinline__ void fma2(u64 &d, u64 a, u64 b) {
    asm("fma.rn.f32x2 %0, %1, %2, %0;" : "+l"(d) : "l"(a), "l"(b));
}
__device__ __forceinline__ void unpack2(float &lo, float &hi, u64 v) {
    asm("mov.b64 {%0, %1}, %2;" : "=f"(lo), "=f"(hi) : "l"(v));
}
__device__ __forceinline__ unsigned smem_u32(const void* p) {
    unsigned a;
    asm("{ .reg .u64 t; cvta.to.shared.u64 t, %1; cvt.u32.u64 %0, t; }" : "=r"(a) : "l"(p));
    return a;
}
__device__ __forceinline__ void bulk_zero(void* gdst, unsigned ssrc, unsigned bytes) {
    asm volatile("cp.async.bulk.global.shared::cta.bulk_group [%0], [%1], %2;"
                 :: "l"(gdst), "r"(ssrc), "r"(bytes) : "memory");
}

// Dynamic smem (36,864 B):
//   sdict float[KK*EE]  32 KB  (natural layout)
//   snrm  float[KK]      2 KB  (-0.5*||d_k||^2)
//   zbuf  float[KK]      2 KB  (zeros; bulk-copy source)
__global__ void __launch_bounds__(NT, 4) vq_kernel(const float* __restrict__ mu,
                                                   const float* __restrict__ dict,
                                                   float* __restrict__ out)
{
    extern __shared__ float smem_f[];
    float* sdict = smem_f;
    float* snrm  = smem_f + KK * EE;
    float* zbuf  = smem_f + KK * EE + KK;

    const int c = blockIdx.x;
    const int t = threadIdx.x;

    // ---- this thread's 4 batch rows, packed pairwise over e ----
    u64 muA[EE / 2], muB[EE / 2], muC[EE / 2], muD[EE / 2];
    {
        const float* m0 = mu + (size_t)(t)       * (CC * EE) + c * EE;
        const float* m1 = mu + (size_t)(t + 128) * (CC * EE) + c * EE;
        const float* m2 = mu + (size_t)(t + 256) * (CC * EE) + c * EE;
        const float* m3 = mu + (size_t)(t + 384) * (CC * EE) + c * EE;
#pragma unroll
        for (int e = 0; e < EE; e += 4) {
            float4 a = *(const float4*)(m0 + e);
            float4 b = *(const float4*)(m1 + e);
            float4 x = *(const float4*)(m2 + e);
            float4 y = *(const float4*)(m3 + e);
            muA[e / 2] = pack2(a.x, a.y);  muA[e / 2 + 1] = pack2(a.z, a.w);
            muB[e / 2] = pack2(b.x, b.y);  muB[e / 2 + 1] = pack2(b.z, b.w);
            muC[e / 2] = pack2(x.x, x.y);  muC[e / 2 + 1] = pack2(x.z, x.w);
            muD[e / 2] = pack2(y.x, y.y);  muD[e / 2 + 1] = pack2(y.z, y.w);
        }
    }

    // ---- dict[c] -> smem; zero zbuf ----
    {
        const float4* g = (const float4*)(dict + (size_t)c * KK * EE);
        float4* sd4 = (float4*)sdict;
#pragma unroll 4
        for (int i = t; i < KK * EE / 4; i += NT) sd4[i] = g[i];
        ((float4*)zbuf)[t] = make_float4(0.f, 0.f, 0.f, 0.f);
    }
    __syncthreads();

    // ---- -0.5 * ||d_k||^2 ----
#pragma unroll
    for (int k = t; k < KK; k += NT) {
        const float4* dv = (const float4*)(sdict + k * EE);
        float s = 0.f;
#pragma unroll
        for (int j = 0; j < 4; j++) {
            float4 v = dv[j];
            s = fmaf(v.x, v.x, s); s = fmaf(v.y, v.y, s);
            s = fmaf(v.z, v.z, s); s = fmaf(v.w, v.w, s);
        }
        snrm[k] = -0.5f * s;
    }
    __syncthreads();

    const unsigned zsrc = smem_u32(zbuf);
    if (t == 0) asm volatile("fence.proxy.async;" ::: "memory");

    // ---- main loop over k; thread 0 streams one bulk zero (2 KB row) per k ----
    float best0 = -3.4e38f, best1 = -3.4e38f, best2 = -3.4e38f, best3 = -3.4e38f;
    int i0 = 0, i1 = 0, i2 = 0, i3 = 0;
    char* ohrow = (char*)(out + OH_OFF + (size_t)c * KK);

#pragma unroll 2
    for (int k = 0; k < KK; ++k) {
        if (t == 0) {
            bulk_zero(ohrow, zsrc, KK * 4);           // zero one_hot[b=k, c, :]
            ohrow += (size_t)CC * KK * 4;
        }
        const u64 init = pack2(snrm[k], 0.0f);
        u64 a0 = init, a1 = init, a2 = init, a3 = init;
        const ulonglong2* q = (const ulonglong2*)(sdict + k * EE);
        ulonglong2 q0 = q[0], q1 = q[1], q2 = q[2], q3 = q[3];

        fma2(a0, muA[0], q0.x); fma2(a1, muB[0], q0.x); fma2(a2, muC[0], q0.x); fma2(a3, muD[0], q0.x);
        fma2(a0, muA[1], q0.y); fma2(a1, muB[1], q0.y); fma2(a2, muC[1], q0.y); fma2(a3, muD[1], q0.y);
        fma2(a0, muA[2], q1.x); fma2(a1, muB[2], q1.x); fma2(a2, muC[2], q1.x); fma2(a3, muD[2], q1.x);
        fma2(a0, muA[3], q1.y); fma2(a1, muB[3], q1.y); fma2(a2, muC[3], q1.y); fma2(a3, muD[3], q1.y);
        fma2(a0, muA[4], q2.x); fma2(a1, muB[4], q2.x); fma2(a2, muC[4], q2.x); fma2(a3, muD[4], q2.x);
        fma2(a0, muA[5], q2.y); fma2(a1, muB[5], q2.y); fma2(a2, muC[5], q2.y); fma2(a3, muD[5], q2.y);
        fma2(a0, muA[6], q3.x); fma2(a1, muB[6], q3.x); fma2(a2, muC[6], q3.x); fma2(a3, muD[6], q3.x);
        fma2(a0, muA[7], q3.y); fma2(a1, muB[7], q3.y); fma2(a2, muC[7], q3.y); fma2(a3, muD[7], q3.y);

        float lo, hi, s;
        unpack2(lo, hi, a0); s = lo + hi; if (s > best0) { best0 = s; i0 = k; }
        unpack2(lo, hi, a1); s = lo + hi; if (s > best1) { best1 = s; i1 = k; }
        unpack2(lo, hi, a2); s = lo + hi; if (s > best2) { best2 = s; i2 = k; }
        unpack2(lo, hi, a3); s = lo + hi; if (s > best3) { best3 = s; i3 = k; }
    }

    // ---- drain bulk zeros, then write outputs ----
    if (t == 0) {
        asm volatile("cp.async.bulk.commit_group;" ::: "memory");
        asm volatile("cp.async.bulk.wait_group 0;" ::: "memory");
    }
    __syncthreads();

    const int   rows[4] = { t, t + 128, t + 256, t + 384 };
    const int   idxs[4] = { i0, i1, i2, i3 };
    const u64*  mus[4]  = { muA, muB, muC, muD };
#pragma unroll
    for (int r = 0; r < 4; ++r) {
        const float* v = sdict + idxs[r] * EE;
        size_t off = (size_t)rows[r] * (CC * EE) + c * EE;
#pragma unroll
        for (int e = 0; e < EE; e += 4) {
            float4 vv = *(const float4*)(v + e);
            float mx, my, mz, mw;
            unpack2(mx, my, mus[r][e / 2]);
            unpack2(mz, mw, mus[r][e / 2 + 1]);
            float4 zz;
            zz.x = mx + (vv.x - mx); zz.y = my + (vv.y - my);
            zz.z = mz + (vv.z - mz); zz.w = mw + (vv.w - mw);
            *(float4*)(out + Z_OFF  + off + e) = zz;
            *(float4*)(out + ZE_OFF + off + e) = vv;
        }
        out[OH_OFF + (size_t)rows[r] * (CC * KK) + (size_t)c * KK + idxs[r]] = 1.0f;
    }
}

extern "C" void kernel_launch(void* const* d_in, const int* in_sizes, int n_in,
                              void* d_out, int out_size)
{
    (void)in_sizes; (void)n_in; (void)out_size;
    const float* mu   = (const float*)d_in[0];
    const float* dict = (const float*)d_in[1];
    float* out = (float*)d_out;

    const int smem = (KK * EE + 2 * KK) * 4;   // 36,864 bytes
    cudaFuncSetAttribute(vq_kernel, cudaFuncAttributeMaxDynamicSharedMemorySize, smem);
    vq_kernel<<<CC, NT, smem>>>(mu, dict, out);
}